// round 9
// baseline (speedup 1.0000x reference)
#include <cuda_runtime.h>
#include <cstdint>
#include <cstddef>

#define Bn 128
#define Tn 2048
#define Cn 128
#define TSTRIDE 132  // padded row stride for transposed transitions in smem (backward)

// Scratch: all forward alphas (exact fp32). __device__ global (no runtime alloc).
__device__ __align__(16) float g_alpha[(size_t)Bn * Tn * Cn];

__device__ __forceinline__ unsigned long long pack2(float lo, float hi) {
    unsigned long long r;
    asm("mov.b64 %0, {%1, %2};" : "=l"(r) : "f"(lo), "f"(hi));
    return r;
}
__device__ __forceinline__ unsigned long long add2(unsigned long long a, unsigned long long b) {
    unsigned long long r;
    asm("add.rn.f32x2 %0, %1, %2;" : "=l"(r) : "l"(a), "l"(b));
    return r;
}
__device__ __forceinline__ float lo32(unsigned long long v) {
    return __uint_as_float((unsigned)v);
}
__device__ __forceinline__ float hi32(unsigned long long v) {
    return __uint_as_float((unsigned)(v >> 32));
}

__device__ __forceinline__ float4 f4max(float4 a, float4 b) {
    return make_float4(fmaxf(a.x, b.x), fmaxf(a.y, b.y),
                       fmaxf(a.z, b.z), fmaxf(a.w, b.w));
}

// ============================ FORWARD ============================
// 2 batches per CTA: thread = (b2, j, c); c in {0,1} splits i into halves of 64.
__global__ __launch_bounds__(512, 1)
void viterbi_fwd(const float* __restrict__ pot,
                 const float* __restrict__ trans) {
    __shared__ __align__(16) float sb[2][2][Cn];  // [parity][b2][j]

    const int tid = threadIdx.x;
    const int c = tid & 1;            // i-half
    const int j = (tid >> 1) & 127;   // class
    const int b2 = tid >> 8;          // batch-within-CTA
    const int b = blockIdx.x * 2 + b2;

    // Per-thread transition regs: i = 64c + 4g + {0..3}, column j, packed.
    unsigned long long tr2[32];
    #pragma unroll
    for (int g = 0; g < 16; ++g) {
        int i0 = 64 * c + 4 * g;
        tr2[2 * g]     = pack2(trans[(i0 + 0) * Cn + j], trans[(i0 + 1) * Cn + j]);
        tr2[2 * g + 1] = pack2(trans[(i0 + 2) * Cn + j], trans[(i0 + 3) * Cn + j]);
    }

    const float* potp = pot + (size_t)b * Tn * Cn + j;
    float* aout = g_alpha + (size_t)b * Tn * Cn + j;

    // t = 0: c0 -> smem row, c1 -> gmem row
    float a0 = potp[0];
    if (c == 0) sb[0][b2][j] = a0;
    else        aout[0] = a0;

    // Potentials prefetch ring (distance 4), clamped index: no guard branches ever.
    float pr[4];
    pr[1] = potp[(size_t)1 * Cn];
    pr[2] = potp[(size_t)2 * Cn];
    pr[3] = potp[(size_t)3 * Cn];
    pr[0] = potp[(size_t)4 * Cn];

    __syncthreads();

    const float NEG_INF = __int_as_float(0xff800000);
    int p = 0;

    auto step = [&](int t) {
        float potv = pr[t & 3];
        pr[t & 3] = potp[(size_t)min(t + 4, Tn - 1) * Cn];  // clamp, branch-free

        const ulonglong2* ab = (const ulonglong2*)(sb[p][b2]) + 16 * c;
        float m0 = NEG_INF, m1 = NEG_INF, m2 = NEG_INF, m3 = NEG_INF;
        #pragma unroll
        for (int g = 0; g < 16; ++g) {
            ulonglong2 a = ab[g];  // 16B: alpha[64c+4g .. +3]
            unsigned long long s01 = add2(a.x, tr2[2 * g]);
            unsigned long long s23 = add2(a.y, tr2[2 * g + 1]);
            m0 = fmaxf(m0, lo32(s01));
            m1 = fmaxf(m1, hi32(s01));
            m2 = fmaxf(m2, lo32(s23));
            m3 = fmaxf(m3, hi32(s23));
        }
        float best = fmaxf(fmaxf(m0, m1), fmaxf(m2, m3));
        // combine the two i-halves (lane pair 2k/2k+1 share j)
        best = fmaxf(best, __shfl_xor_sync(0xffffffffu, best, 1));

        float alpha = best + potv;
        if (c == 0) sb[p ^ 1][b2][j] = alpha;       // @P STS
        else        aout[(size_t)t * Cn] = alpha;   // @P STG
        __syncthreads();
        p ^= 1;
    };

    // Main: t = 1 .. 2044 (511 branch-free blocks of 4), tail 3 steps.
    for (int tb = 1; tb <= Tn - 7; tb += 4) {
        step(tb + 0);
        step(tb + 1);
        step(tb + 2);
        step(tb + 3);
    }
    step(Tn - 3);
    step(Tn - 2);
    step(Tn - 1);
}

// ============================ BACKWARD ============================
// Argmax over 128 values, 8 active lanes x 16 values (lane L -> j = 16L..16L+15).
// Float-native FMNMX + numeric-equality tie-break; returns SMALLEST j achieving
// the max (matches jnp.argmax first-occurrence, -0/+0 compare equal numerically).
__device__ __forceinline__ int argmax128_g8(const float4 s0, const float4 s1,
                                            const float4 s2, const float4 s3) {
    float4 q = f4max(f4max(s0, s1), f4max(s2, s3));
    float m = fmaxf(fmaxf(q.x, q.y), fmaxf(q.z, q.w));

    float wm = m;
    wm = fmaxf(wm, __shfl_xor_sync(0xffffffffu, wm, 4));
    wm = fmaxf(wm, __shfl_xor_sync(0xffffffffu, wm, 2));
    wm = fmaxf(wm, __shfl_xor_sync(0xffffffffu, wm, 1));

    // In-lane first slot equal to m (depends only on m: overlaps butterfly latency).
    int i0  = (s0.x == m) ? 0  : 99;
    int i1  = (s0.y == m) ? 1  : 99;
    int i2  = (s0.z == m) ? 2  : 99;
    int i3  = (s0.w == m) ? 3  : 99;
    int i4  = (s1.x == m) ? 4  : 99;
    int i5  = (s1.y == m) ? 5  : 99;
    int i6  = (s1.z == m) ? 6  : 99;
    int i7  = (s1.w == m) ? 7  : 99;
    int i8  = (s2.x == m) ? 8  : 99;
    int i9  = (s2.y == m) ? 9  : 99;
    int i10 = (s2.z == m) ? 10 : 99;
    int i11 = (s2.w == m) ? 11 : 99;
    int i12 = (s3.x == m) ? 12 : 99;
    int i13 = (s3.y == m) ? 13 : 99;
    int i14 = (s3.z == m) ? 14 : 99;
    int i15 = (s3.w == m) ? 15 : 99;
    int loc = min(min(min(min(i0, i1), min(i2, i3)), min(min(i4, i5), min(i6, i7))),
                  min(min(min(i8, i9), min(i10, i11)), min(min(i12, i13), min(i14, i15))));

    unsigned ball = __ballot_sync(0xffffffffu, m == wm) & 0xffu;  // lanes 0..7 only
    int lane = __ffs((int)ball) - 1;
    int locw = __shfl_sync(0xffffffffu, loc, lane);
    return 16 * lane + locw;
}

__global__ __launch_bounds__(128, 1)
void viterbi_bwd(const float* __restrict__ trans,
                 float* __restrict__ out) {
    extern __shared__ float tT[];  // [Cn][TSTRIDE]: tT[j*TSTRIDE + i] = trans[i][j]

    const int b = blockIdx.x;
    const int tid = threadIdx.x;

    // Build transposed transitions in smem (coalesced reads across tid).
    {
        int j0 = tid;  // 0..127
        #pragma unroll 8
        for (int i = 0; i < Cn; ++i) {
            tT[j0 * TSTRIDE + i] = trans[i * Cn + j0];
        }
    }
    __syncthreads();

    if (tid < 32) {
        const int l = tid;
        const int ll = min(l, 7);     // lanes 8..31 duplicate lane 7 (ignored by ballot)
        float* ob = out + (size_t)b * Tn;
        const float4* arow = (const float4*)(g_alpha + (size_t)b * Tn * Cn);

        int tag;
        // last tag = argmax over alpha_{T-1}
        {
            float4 V0 = arow[(size_t)(Tn - 1) * 32 + 4 * ll + 0];
            float4 V1 = arow[(size_t)(Tn - 1) * 32 + 4 * ll + 1];
            float4 V2 = arow[(size_t)(Tn - 1) * 32 + 4 * ll + 2];
            float4 V3 = arow[(size_t)(Tn - 1) * 32 + 4 * ll + 3];
            tag = argmax128_g8(V0, V1, V2, V3);
        }
        if (l == 0) ob[Tn - 1] = (float)tag;

        // Prefetch ring: pf[u] = alpha row (2046 - u), depth 6.
        float4 pf[6][4];
        #pragma unroll
        for (int u = 0; u < 6; ++u) {
            #pragma unroll
            for (int k = 0; k < 4; ++k) {
                pf[u][k] = arow[(size_t)(Tn - 2 - u) * 32 + 4 * ll + k];
            }
        }

        auto tstep = [&](int t, int u) {
            float4 A0 = pf[u][0], A1 = pf[u][1], A2 = pf[u][2], A3 = pf[u][3];
            // Refill slot u with row max(t-6, 0): clamped, branch-free.
            size_t pidx = (size_t)max(t - 6, 0) * 32 + 4 * ll;
            pf[u][0] = arow[pidx + 0];
            pf[u][1] = arow[pidx + 1];
            pf[u][2] = arow[pidx + 2];
            pf[u][3] = arow[pidx + 3];

            const float4* trow = (const float4*)(tT + tag * TSTRIDE);
            float4 T0 = trow[4 * ll + 0];
            float4 T1 = trow[4 * ll + 1];
            float4 T2 = trow[4 * ll + 2];
            float4 T3 = trow[4 * ll + 3];

            float4 s0 = make_float4(A0.x + T0.x, A0.y + T0.y, A0.z + T0.z, A0.w + T0.w);
            float4 s1 = make_float4(A1.x + T1.x, A1.y + T1.y, A1.z + T1.z, A1.w + T1.w);
            float4 s2 = make_float4(A2.x + T2.x, A2.y + T2.y, A2.z + T2.z, A2.w + T2.w);
            float4 s3 = make_float4(A3.x + T3.x, A3.y + T3.y, A3.z + T3.z, A3.w + T3.w);

            tag = argmax128_g8(s0, s1, s2, s3);
            if (l == 0) ob[t] = (float)tag;   // @P STG
        };

        // Main: t = 2046 .. 1 (341 branch-free blocks of 6).
        for (int tb = Tn - 2; tb >= 6; tb -= 6) {
            #pragma unroll
            for (int u = 0; u < 6; ++u) {
                tstep(tb - u, u);
            }
        }
        // Final step t = 0: row 0 is in pf[0].
        {
            float4 A0 = pf[0][0], A1 = pf[0][1], A2 = pf[0][2], A3 = pf[0][3];
            const float4* trow = (const float4*)(tT + tag * TSTRIDE);
            float4 T0 = trow[4 * ll + 0];
            float4 T1 = trow[4 * ll + 1];
            float4 T2 = trow[4 * ll + 2];
            float4 T3 = trow[4 * ll + 3];
            float4 s0 = make_float4(A0.x + T0.x, A0.y + T0.y, A0.z + T0.z, A0.w + T0.w);
            float4 s1 = make_float4(A1.x + T1.x, A1.y + T1.y, A1.z + T1.z, A1.w + T1.w);
            float4 s2 = make_float4(A2.x + T2.x, A2.y + T2.y, A2.z + T2.z, A2.w + T2.w);
            float4 s3 = make_float4(A3.x + T3.x, A3.y + T3.y, A3.z + T3.z, A3.w + T3.w);
            tag = argmax128_g8(s0, s1, s2, s3);
            if (l == 0) ob[0] = (float)tag;
        }
    }
}

extern "C" void kernel_launch(void* const* d_in, const int* in_sizes, int n_in,
                              void* d_out, int out_size) {
    const float* inputs = (const float*)d_in[0];       // [B, T, C] f32
    const float* transitions = (const float*)d_in[1];  // [C, C] f32
    float* out = (float*)d_out;                        // [B, T] f32 (tags)

    viterbi_fwd<<<Bn / 2, 512>>>(inputs, transitions);

    const int bwd_smem = Cn * TSTRIDE * (int)sizeof(float);  // ~67.6KB
    cudaFuncSetAttribute(viterbi_bwd, cudaFuncAttributeMaxDynamicSharedMemorySize, bwd_smem);
    viterbi_bwd<<<Bn, 128, bwd_smem>>>(transitions, out);
}